// round 2
// baseline (speedup 1.0000x reference)
#include <cuda_runtime.h>
#include <cuda_bf16.h>
#include <math.h>

#define N_NODES 50000
#define N_EDGES 500000
#define D 128
#define BN_EPS 1e-5f

// ---------------- scratch (static device globals; no allocation) ----------------
__device__ float g_P[(size_t)N_NODES * 512];    // [PF1|PF2|PS1|PS2] per node
__device__ float g_EA[(size_t)N_EDGES * 256];   // [EAf|EAs] per edge
__device__ float g_agg[(size_t)N_NODES * D];    // scatter-sum target
__device__ float g_B1[128 * 512];               // repacked node weights
__device__ float g_B2[128 * 256];               // repacked edge weights
__device__ float g_stats[2 * D];                // [sum | sumsq]

// ---------------- weight repack ----------------
// Wf, Ws are [384, 128] row-major (in, out).
// B1[k, j]: j<128 -> Wf[k, j]; j<256 -> Wf[128+k, j-128]; j<384 -> Ws[k, j-256]; else Ws[128+k, j-384]
// B2[k, j]: j<128 -> Wf[256+k, j]; else Ws[256+k, j-128]
__global__ void prep_weights(const float* __restrict__ Wf, const float* __restrict__ Ws) {
    int i = blockIdx.x * blockDim.x + threadIdx.x;
    if (i < 128 * 512) {
        int k = i >> 9, j = i & 511;
        float v;
        if (j < 128)      v = Wf[k * 128 + j];
        else if (j < 256) v = Wf[(128 + k) * 128 + (j - 128)];
        else if (j < 384) v = Ws[k * 128 + (j - 256)];
        else              v = Ws[(128 + k) * 128 + (j - 384)];
        g_B1[i] = v;
    }
    if (i < 128 * 256) {
        int k = i >> 8, j = i & 255;
        g_B2[i] = (j < 128) ? Wf[(256 + k) * 128 + j] : Ws[(256 + k) * 128 + (j - 128)];
    }
}

// ---------------- zero scratch ----------------
__global__ void zero_scratch() {
    size_t total = (size_t)N_NODES * D;
    float4* p = reinterpret_cast<float4*>(g_agg);
    size_t n4 = total / 4;
    for (size_t i = blockIdx.x * blockDim.x + threadIdx.x; i < n4; i += (size_t)gridDim.x * blockDim.x)
        p[i] = make_float4(0.f, 0.f, 0.f, 0.f);
    int t = blockIdx.x * blockDim.x + threadIdx.x;
    if (t < 2 * D) g_stats[t] = 0.f;
}

// ---------------- SGEMM: C[M,N] = A[M,128] @ B[128,N], row-major ----------------
// B and C are bound to device globals via template to avoid taking the address
// of a __device__ variable in host code (that was the R1 correctness bug).
// WHICH=0: B=g_B1, C=g_P,  N=512.   WHICH=1: B=g_B2, C=g_EA, N=256.
#define BM 64
#define BN 64
#define BK 16
template <int WHICH>
__global__ __launch_bounds__(256) void gemm_k128(const float* __restrict__ A, int M)
{
    const float* __restrict__ B = (WHICH == 0) ? g_B1 : g_B2;
    float* __restrict__ C       = (WHICH == 0) ? g_P  : g_EA;
    const int N                 = (WHICH == 0) ? 512  : 256;

    __shared__ float As[BK][BM];  // transposed A tile
    __shared__ float Bs[BK][BN];

    const int tid = threadIdx.x;
    const int row0 = blockIdx.y * BM;
    const int col0 = blockIdx.x * BN;
    const int tr = tid >> 4;          // 0..15
    const int tc = tid & 15;          // 0..15

    // global-load indexing
    const int a_r  = tid >> 2;        // 0..63
    const int a_c4 = (tid & 3) * 4;   // 0,4,8,12
    const int b_r  = tid >> 4;        // 0..15
    const int b_c4 = (tid & 15) * 4;

    float acc[4][4];
#pragma unroll
    for (int i = 0; i < 4; i++)
#pragma unroll
        for (int j = 0; j < 4; j++) acc[i][j] = 0.f;

    const int ar = row0 + a_r;
    for (int k0 = 0; k0 < 128; k0 += BK) {
        float4 av = make_float4(0.f, 0.f, 0.f, 0.f);
        if (ar < M) av = *reinterpret_cast<const float4*>(A + (size_t)ar * 128 + k0 + a_c4);
        As[a_c4 + 0][a_r] = av.x;
        As[a_c4 + 1][a_r] = av.y;
        As[a_c4 + 2][a_r] = av.z;
        As[a_c4 + 3][a_r] = av.w;

        float4 bv = *reinterpret_cast<const float4*>(B + (size_t)(k0 + b_r) * N + col0 + b_c4);
        *reinterpret_cast<float4*>(&Bs[b_r][b_c4]) = bv;
        __syncthreads();

#pragma unroll
        for (int k = 0; k < BK; k++) {
            float4 a = *reinterpret_cast<float4*>(&As[k][tr * 4]);
            float4 b = *reinterpret_cast<float4*>(&Bs[k][tc * 4]);
            acc[0][0] += a.x * b.x; acc[0][1] += a.x * b.y; acc[0][2] += a.x * b.z; acc[0][3] += a.x * b.w;
            acc[1][0] += a.y * b.x; acc[1][1] += a.y * b.y; acc[1][2] += a.y * b.z; acc[1][3] += a.y * b.w;
            acc[2][0] += a.z * b.x; acc[2][1] += a.z * b.y; acc[2][2] += a.z * b.z; acc[2][3] += a.z * b.w;
            acc[3][0] += a.w * b.x; acc[3][1] += a.w * b.y; acc[3][2] += a.w * b.z; acc[3][3] += a.w * b.w;
        }
        __syncthreads();
    }

#pragma unroll
    for (int i = 0; i < 4; i++) {
        int row = row0 + tr * 4 + i;
        if (row < M) {
            float4 v = make_float4(acc[i][0], acc[i][1], acc[i][2], acc[i][3]);
            *reinterpret_cast<float4*>(C + (size_t)row * N + col0 + tc * 4) = v;
        }
    }
}

// ---------------- edge gating + scatter ----------------
__device__ __forceinline__ float sigmoidf_(float x) { return 1.f / (1.f + expf(-x)); }
__device__ __forceinline__ float softplusf_(float x) {
    return fmaxf(x, 0.f) + log1pf(expf(-fabsf(x)));
}

__global__ __launch_bounds__(256) void edge_kernel(
    const int* __restrict__ src, const int* __restrict__ tgt,
    const float* __restrict__ bf, const float* __restrict__ bs)
{
    const int gwarp = (blockIdx.x * blockDim.x + threadIdx.x) >> 5;
    const int lane = threadIdx.x & 31;
    if (gwarp >= N_EDGES) return;
    const int e = gwarp;

    const int s = src[e];
    const int t = tgt[e];

    const float4 eaf = *reinterpret_cast<const float4*>(g_EA + (size_t)e * 256 + lane * 4);
    const float4 eas = *reinterpret_cast<const float4*>(g_EA + (size_t)e * 256 + 128 + lane * 4);
    const float4 pf1 = *reinterpret_cast<const float4*>(g_P + (size_t)s * 512 + 0   + lane * 4);
    const float4 pf2 = *reinterpret_cast<const float4*>(g_P + (size_t)t * 512 + 128 + lane * 4);
    const float4 ps1 = *reinterpret_cast<const float4*>(g_P + (size_t)s * 512 + 256 + lane * 4);
    const float4 ps2 = *reinterpret_cast<const float4*>(g_P + (size_t)t * 512 + 384 + lane * 4);
    const float4 bfv = *reinterpret_cast<const float4*>(bf + lane * 4);
    const float4 bsv = *reinterpret_cast<const float4*>(bs + lane * 4);

    float f0 = eaf.x + pf1.x + pf2.x + bfv.x;
    float f1 = eaf.y + pf1.y + pf2.y + bfv.y;
    float f2 = eaf.z + pf1.z + pf2.z + bfv.z;
    float f3 = eaf.w + pf1.w + pf2.w + bfv.w;
    float s0 = eas.x + ps1.x + ps2.x + bsv.x;
    float s1 = eas.y + ps1.y + ps2.y + bsv.y;
    float s2 = eas.z + ps1.z + ps2.z + bsv.z;
    float s3 = eas.w + ps1.w + ps2.w + bsv.w;

    float m0 = sigmoidf_(f0) * softplusf_(s0);
    float m1 = sigmoidf_(f1) * softplusf_(s1);
    float m2 = sigmoidf_(f2) * softplusf_(s2);
    float m3 = sigmoidf_(f3) * softplusf_(s3);

    float* dst = g_agg + (size_t)s * D + lane * 4;
    atomicAdd(dst + 0, m0);
    atomicAdd(dst + 1, m1);
    atomicAdd(dst + 2, m2);
    atomicAdd(dst + 3, m3);
}

// ---------------- BN stats ----------------
__global__ __launch_bounds__(128) void bn_stats() {
    const int d = threadIdx.x;  // 0..127
    float sum = 0.f, sq = 0.f;
    for (int n = blockIdx.x; n < N_NODES; n += gridDim.x) {
        float v = g_agg[(size_t)n * D + d];
        sum += v;
        sq += v * v;
    }
    atomicAdd(&g_stats[d], sum);
    atomicAdd(&g_stats[D + d], sq);
}

// ---------------- BN apply + residual + softplus ----------------
__global__ __launch_bounds__(256) void final_kernel(
    const float* __restrict__ x, const float* __restrict__ gamma,
    const float* __restrict__ beta, float* __restrict__ out)
{
    const float invN = 1.0f / (float)N_NODES;
    for (size_t idx = (size_t)blockIdx.x * blockDim.x + threadIdx.x;
         idx < (size_t)N_NODES * D;
         idx += (size_t)gridDim.x * blockDim.x) {
        int d = (int)(idx & (D - 1));
        float mean = g_stats[d] * invN;
        float var = g_stats[D + d] * invN - mean * mean;
        float rstd = rsqrtf(var + BN_EPS);
        float a = (g_agg[idx] - mean) * rstd * gamma[d] + beta[d];
        float v = x[idx] + a;
        out[idx] = softplusf_(v);
    }
}

// ---------------- launch ----------------
extern "C" void kernel_launch(void* const* d_in, const int* in_sizes, int n_in,
                              void* d_out, int out_size) {
    const float* x         = (const float*)d_in[0];
    const float* edge_attr = (const float*)d_in[1];
    const int*   edge_src  = (const int*)d_in[2];
    const int*   edge_tgt  = (const int*)d_in[3];
    const float* Wf        = (const float*)d_in[4];
    const float* bf        = (const float*)d_in[5];
    const float* Ws        = (const float*)d_in[6];
    const float* bs        = (const float*)d_in[7];
    const float* gamma     = (const float*)d_in[8];
    const float* beta      = (const float*)d_in[9];
    float* out = (float*)d_out;

    // 1. repack weights
    prep_weights<<<(128 * 512 + 255) / 256, 256>>>(Wf, Ws);

    // 2. zero agg + stats
    zero_scratch<<<4096, 256>>>();

    // 3. node GEMM: P[50000, 512] = x @ B1
    {
        dim3 grid(512 / BN, (N_NODES + BM - 1) / BM);
        gemm_k128<0><<<grid, 256>>>(x, N_NODES);
    }

    // 4. edge GEMM: EA[500000, 256] = edge_attr @ B2
    {
        dim3 grid(256 / BN, (N_EDGES + BM - 1) / BM);
        gemm_k128<1><<<grid, 256>>>(edge_attr, N_EDGES);
    }

    // 5. edge gating + scatter (1 warp per edge)
    {
        int warps_per_block = 256 / 32;
        int blocks = (N_EDGES + warps_per_block - 1) / warps_per_block;
        edge_kernel<<<blocks, 256>>>(edge_src, edge_tgt, bf, bs);
    }

    // 6. BN stats
    bn_stats<<<512, 128>>>();

    // 7. BN apply + residual + softplus
    final_kernel<<<(N_NODES * D + 255) / 256, 256>>>(x, gamma, beta, out);
}

// round 3
// speedup vs baseline: 1.2333x; 1.2333x over previous
#include <cuda_runtime.h>
#include <cuda_bf16.h>
#include <math.h>

#define N_NODES 50000
#define N_EDGES 500000
#define D 128
#define BN_EPS 1e-5f

// ---------------- scratch (static device globals; no allocation) ----------------
__device__ float g_P[(size_t)N_NODES * 512];    // [PF1|PF2|PS1|PS2] per node
__device__ float g_agg[(size_t)N_NODES * D];    // scatter-sum target
__device__ float g_B1[128 * 512];               // repacked node weights
__device__ float g_B2[128 * 256];               // repacked edge weights
__device__ float g_stats[2 * D];                // [sum | sumsq]

// ---------------- weight repack ----------------
__global__ void prep_weights(const float* __restrict__ Wf, const float* __restrict__ Ws) {
    int i = blockIdx.x * blockDim.x + threadIdx.x;
    if (i < 128 * 512) {
        int k = i >> 9, j = i & 511;
        float v;
        if (j < 128)      v = Wf[k * 128 + j];
        else if (j < 256) v = Wf[(128 + k) * 128 + (j - 128)];
        else if (j < 384) v = Ws[k * 128 + (j - 256)];
        else              v = Ws[(128 + k) * 128 + (j - 384)];
        g_B1[i] = v;
    }
    if (i < 128 * 256) {
        int k = i >> 8, j = i & 255;
        g_B2[i] = (j < 128) ? Wf[(256 + k) * 128 + j] : Ws[(256 + k) * 128 + (j - 128)];
    }
}

// ---------------- zero scratch ----------------
__global__ void zero_scratch() {
    size_t total = (size_t)N_NODES * D;
    float4* p = reinterpret_cast<float4*>(g_agg);
    size_t n4 = total / 4;
    for (size_t i = blockIdx.x * blockDim.x + threadIdx.x; i < n4; i += (size_t)gridDim.x * blockDim.x)
        p[i] = make_float4(0.f, 0.f, 0.f, 0.f);
    int t = blockIdx.x * blockDim.x + threadIdx.x;
    if (t < 2 * D) g_stats[t] = 0.f;
}

// ---------------- node SGEMM: g_P[M,512] = x[M,128] @ g_B1[128,512] ----------------
#define BM 64
#define BN 64
#define BK 16
__global__ __launch_bounds__(256) void node_gemm(const float* __restrict__ A, int M)
{
    const float* __restrict__ B = g_B1;
    float* __restrict__ C = g_P;
    const int N = 512;

    __shared__ float As[BK][BM];
    __shared__ float Bs[BK][BN];

    const int tid = threadIdx.x;
    const int row0 = blockIdx.y * BM;
    const int col0 = blockIdx.x * BN;
    const int tr = tid >> 4;
    const int tc = tid & 15;

    const int a_r  = tid >> 2;
    const int a_c4 = (tid & 3) * 4;
    const int b_r  = tid >> 4;
    const int b_c4 = (tid & 15) * 4;

    float acc[4][4];
#pragma unroll
    for (int i = 0; i < 4; i++)
#pragma unroll
        for (int j = 0; j < 4; j++) acc[i][j] = 0.f;

    const int ar = row0 + a_r;
    for (int k0 = 0; k0 < 128; k0 += BK) {
        float4 av = make_float4(0.f, 0.f, 0.f, 0.f);
        if (ar < M) av = *reinterpret_cast<const float4*>(A + (size_t)ar * 128 + k0 + a_c4);
        As[a_c4 + 0][a_r] = av.x;
        As[a_c4 + 1][a_r] = av.y;
        As[a_c4 + 2][a_r] = av.z;
        As[a_c4 + 3][a_r] = av.w;

        float4 bv = *reinterpret_cast<const float4*>(B + (size_t)(k0 + b_r) * N + col0 + b_c4);
        *reinterpret_cast<float4*>(&Bs[b_r][b_c4]) = bv;
        __syncthreads();

#pragma unroll
        for (int k = 0; k < BK; k++) {
            float4 a = *reinterpret_cast<float4*>(&As[k][tr * 4]);
            float4 b = *reinterpret_cast<float4*>(&Bs[k][tc * 4]);
            acc[0][0] += a.x * b.x; acc[0][1] += a.x * b.y; acc[0][2] += a.x * b.z; acc[0][3] += a.x * b.w;
            acc[1][0] += a.y * b.x; acc[1][1] += a.y * b.y; acc[1][2] += a.y * b.z; acc[1][3] += a.y * b.w;
            acc[2][0] += a.z * b.x; acc[2][1] += a.z * b.y; acc[2][2] += a.z * b.z; acc[2][3] += a.z * b.w;
            acc[3][0] += a.w * b.x; acc[3][1] += a.w * b.y; acc[3][2] += a.w * b.z; acc[3][3] += a.w * b.w;
        }
        __syncthreads();
    }

#pragma unroll
    for (int i = 0; i < 4; i++) {
        int row = row0 + tr * 4 + i;
        if (row < M) {
            float4 v = make_float4(acc[i][0], acc[i][1], acc[i][2], acc[i][3]);
            *reinterpret_cast<float4*>(C + (size_t)row * N + col0 + tc * 4) = v;
        }
    }
}

// ---------------- activations ----------------
__device__ __forceinline__ float sigmoidf_(float x) { return 1.f / (1.f + expf(-x)); }
__device__ __forceinline__ float softplusf_(float x) {
    return fmaxf(x, 0.f) + log1pf(expf(-fabsf(x)));
}

// ---------------- fused edge GEMM + gate + scatter ----------------
// Per block: 64 edges x full 256 output cols (f: 0-127, s: 128-255).
// 256 threads = 8 (M groups) x 32 (N groups). Each thread: 8 rows x (4 f-cols + 4 s-cols).
// Thread (tr, tc) owns f-cols [tc*4, tc*4+4) and s-cols [128+tc*4, 128+tc*4+4),
// so the gate sigmoid(f)*softplus(s) is computed entirely in-register.
#define EBM 64
#define EBK 16
__global__ __launch_bounds__(256) void edge_fused(
    const float* __restrict__ A,      // edge_attr [N_EDGES, 128]
    const int* __restrict__ src, const int* __restrict__ tgt,
    const float* __restrict__ bf, const float* __restrict__ bs)
{
    __shared__ float As[EBK][EBM];
    __shared__ float Bs[EBK][256];
    __shared__ int s_src[EBM];
    __shared__ int s_tgt[EBM];

    const int tid = threadIdx.x;
    const int row0 = blockIdx.x * EBM;
    const int tr = tid >> 5;   // 0..7
    const int tc = tid & 31;   // 0..31

    if (tid < EBM) {
        int r = row0 + tid;
        s_src[tid] = (r < N_EDGES) ? src[r] : 0;
        s_tgt[tid] = (r < N_EDGES) ? tgt[r] : 0;
    }

    // A-load indexing: 64 rows x 16 cols per step, 1 float4/thread
    const int a_r  = tid >> 2;          // 0..63
    const int a_c4 = (tid & 3) * 4;     // 0,4,8,12
    // B-load indexing: 16 rows x 256 cols per step, 4 float4/thread
    const int b_r  = tid >> 4;          // 0..15
    const int b_c  = (tid & 15) * 4;    // 0..60

    float acc[8][8];
#pragma unroll
    for (int i = 0; i < 8; i++)
#pragma unroll
        for (int j = 0; j < 8; j++) acc[i][j] = 0.f;

    const int ar = row0 + a_r;
    for (int k0 = 0; k0 < 128; k0 += EBK) {
        float4 av = make_float4(0.f, 0.f, 0.f, 0.f);
        if (ar < N_EDGES) av = *reinterpret_cast<const float4*>(A + (size_t)ar * 128 + k0 + a_c4);
        As[a_c4 + 0][a_r] = av.x;
        As[a_c4 + 1][a_r] = av.y;
        As[a_c4 + 2][a_r] = av.z;
        As[a_c4 + 3][a_r] = av.w;

#pragma unroll
        for (int i = 0; i < 4; i++) {
            int col = b_c + i * 64;
            float4 bv = *reinterpret_cast<const float4*>(g_B2 + (size_t)(k0 + b_r) * 256 + col);
            *reinterpret_cast<float4*>(&Bs[b_r][col]) = bv;
        }
        __syncthreads();

#pragma unroll
        for (int k = 0; k < EBK; k++) {
            float4 a0 = *reinterpret_cast<float4*>(&As[k][tr * 8]);
            float4 a1 = *reinterpret_cast<float4*>(&As[k][tr * 8 + 4]);
            float4 bF = *reinterpret_cast<float4*>(&Bs[k][tc * 4]);
            float4 bS = *reinterpret_cast<float4*>(&Bs[k][tc * 4 + 128]);
            float am[8] = {a0.x, a0.y, a0.z, a0.w, a1.x, a1.y, a1.z, a1.w};
#pragma unroll
            for (int i = 0; i < 8; i++) {
                acc[i][0] += am[i] * bF.x;
                acc[i][1] += am[i] * bF.y;
                acc[i][2] += am[i] * bF.z;
                acc[i][3] += am[i] * bF.w;
                acc[i][4] += am[i] * bS.x;
                acc[i][5] += am[i] * bS.y;
                acc[i][6] += am[i] * bS.z;
                acc[i][7] += am[i] * bS.w;
            }
        }
        __syncthreads();
    }

    // epilogue: gate + scatter
    const float4 bfv = *reinterpret_cast<const float4*>(bf + tc * 4);
    const float4 bsv = *reinterpret_cast<const float4*>(bs + tc * 4);

#pragma unroll
    for (int i = 0; i < 8; i++) {
        int lr = tr * 8 + i;
        int r = row0 + lr;
        if (r >= N_EDGES) break;
        int s = s_src[lr];
        int t = s_tgt[lr];
        const float4 pf1 = *reinterpret_cast<const float4*>(g_P + (size_t)s * 512 + 0   + tc * 4);
        const float4 pf2 = *reinterpret_cast<const float4*>(g_P + (size_t)t * 512 + 128 + tc * 4);
        const float4 ps1 = *reinterpret_cast<const float4*>(g_P + (size_t)s * 512 + 256 + tc * 4);
        const float4 ps2 = *reinterpret_cast<const float4*>(g_P + (size_t)t * 512 + 384 + tc * 4);

        float f0 = acc[i][0] + pf1.x + pf2.x + bfv.x;
        float f1 = acc[i][1] + pf1.y + pf2.y + bfv.y;
        float f2 = acc[i][2] + pf1.z + pf2.z + bfv.z;
        float f3 = acc[i][3] + pf1.w + pf2.w + bfv.w;
        float s0 = acc[i][4] + ps1.x + ps2.x + bsv.x;
        float s1 = acc[i][5] + ps1.y + ps2.y + bsv.y;
        float s2 = acc[i][6] + ps1.z + ps2.z + bsv.z;
        float s3 = acc[i][7] + ps1.w + ps2.w + bsv.w;

        float m0 = sigmoidf_(f0) * softplusf_(s0);
        float m1 = sigmoidf_(f1) * softplusf_(s1);
        float m2 = sigmoidf_(f2) * softplusf_(s2);
        float m3 = sigmoidf_(f3) * softplusf_(s3);

        float* dst = g_agg + (size_t)s * D + tc * 4;
        atomicAdd(dst + 0, m0);
        atomicAdd(dst + 1, m1);
        atomicAdd(dst + 2, m2);
        atomicAdd(dst + 3, m3);
    }
}

// ---------------- BN stats ----------------
__global__ __launch_bounds__(128) void bn_stats() {
    const int d = threadIdx.x;
    float sum = 0.f, sq = 0.f;
    for (int n = blockIdx.x; n < N_NODES; n += gridDim.x) {
        float v = g_agg[(size_t)n * D + d];
        sum += v;
        sq += v * v;
    }
    atomicAdd(&g_stats[d], sum);
    atomicAdd(&g_stats[D + d], sq);
}

// ---------------- BN apply + residual + softplus ----------------
__global__ __launch_bounds__(256) void final_kernel(
    const float* __restrict__ x, const float* __restrict__ gamma,
    const float* __restrict__ beta, float* __restrict__ out)
{
    const float invN = 1.0f / (float)N_NODES;
    for (size_t idx = (size_t)blockIdx.x * blockDim.x + threadIdx.x;
         idx < (size_t)N_NODES * D;
         idx += (size_t)gridDim.x * blockDim.x) {
        int d = (int)(idx & (D - 1));
        float mean = g_stats[d] * invN;
        float var = g_stats[D + d] * invN - mean * mean;
        float rstd = rsqrtf(var + BN_EPS);
        float a = (g_agg[idx] - mean) * rstd * gamma[d] + beta[d];
        float v = x[idx] + a;
        out[idx] = softplusf_(v);
    }
}

// ---------------- launch ----------------
extern "C" void kernel_launch(void* const* d_in, const int* in_sizes, int n_in,
                              void* d_out, int out_size) {
    const float* x         = (const float*)d_in[0];
    const float* edge_attr = (const float*)d_in[1];
    const int*   edge_src  = (const int*)d_in[2];
    const int*   edge_tgt  = (const int*)d_in[3];
    const float* Wf        = (const float*)d_in[4];
    const float* bf        = (const float*)d_in[5];
    const float* Ws        = (const float*)d_in[6];
    const float* bs        = (const float*)d_in[7];
    const float* gamma     = (const float*)d_in[8];
    const float* beta      = (const float*)d_in[9];
    float* out = (float*)d_out;

    // 1. repack weights
    prep_weights<<<(128 * 512 + 255) / 256, 256>>>(Wf, Ws);

    // 2. zero agg + stats
    zero_scratch<<<4096, 256>>>();

    // 3. node GEMM: P[50000, 512] = x @ B1
    {
        dim3 grid(512 / BN, (N_NODES + BM - 1) / BM);
        node_gemm<<<grid, 256>>>(x, N_NODES);
    }

    // 4. fused edge GEMM + gate + scatter
    {
        int blocks = (N_EDGES + EBM - 1) / EBM;
        edge_fused<<<blocks, 256>>>(edge_attr, edge_src, edge_tgt, bf, bs);
    }

    // 5. BN stats
    bn_stats<<<512, 128>>>();

    // 6. BN apply + residual + softplus
    final_kernel<<<(N_NODES * D + 255) / 256, 256>>>(x, gamma, beta, out);
}

// round 4
// speedup vs baseline: 1.3519x; 1.0962x over previous
#include <cuda_runtime.h>
#include <cuda_bf16.h>
#include <math.h>

#define N_NODES 50000
#define N_EDGES 500000
#define D 128
#define BN_EPS 1e-5f

// ---------------- scratch (static device globals; no allocation) ----------------
__device__ float g_P[(size_t)N_NODES * 512];    // [PF1|PF2|PS1|PS2] per node
__device__ float g_agg[(size_t)N_NODES * D];    // scatter-sum target
__device__ float g_B1[128 * 512];               // repacked node weights
__device__ float g_B2[128 * 256];               // repacked edge weights
__device__ float g_stats[2 * D];                // [sum | sumsq]

// ---------------- f32x2 helpers (Blackwell packed fp32) ----------------
__device__ __forceinline__ unsigned long long pack2(float lo, float hi) {
    unsigned long long r;
    asm("mov.b64 %0, {%1, %2};" : "=l"(r) : "f"(lo), "f"(hi));
    return r;
}
__device__ __forceinline__ void unpack2(unsigned long long v, float& lo, float& hi) {
    asm("mov.b64 {%0, %1}, %2;" : "=f"(lo), "=f"(hi) : "l"(v));
}
__device__ __forceinline__ void fma2(unsigned long long& acc, unsigned long long a, unsigned long long b) {
    asm("fma.rn.f32x2 %0, %1, %2, %0;" : "+l"(acc) : "l"(a), "l"(b));
}

// ---------------- weight repack ----------------
__global__ void prep_weights(const float* __restrict__ Wf, const float* __restrict__ Ws) {
    int i = blockIdx.x * blockDim.x + threadIdx.x;
    if (i < 128 * 512) {
        int k = i >> 9, j = i & 511;
        float v;
        if (j < 128)      v = Wf[k * 128 + j];
        else if (j < 256) v = Wf[(128 + k) * 128 + (j - 128)];
        else if (j < 384) v = Ws[k * 128 + (j - 256)];
        else              v = Ws[(128 + k) * 128 + (j - 384)];
        g_B1[i] = v;
    }
    if (i < 128 * 256) {
        int k = i >> 8, j = i & 255;
        g_B2[i] = (j < 128) ? Wf[(256 + k) * 128 + j] : Ws[(256 + k) * 128 + (j - 128)];
    }
}

// ---------------- zero scratch ----------------
__global__ void zero_scratch() {
    size_t total = (size_t)N_NODES * D;
    float4* p = reinterpret_cast<float4*>(g_agg);
    size_t n4 = total / 4;
    for (size_t i = blockIdx.x * blockDim.x + threadIdx.x; i < n4; i += (size_t)gridDim.x * blockDim.x)
        p[i] = make_float4(0.f, 0.f, 0.f, 0.f);
    int t = blockIdx.x * blockDim.x + threadIdx.x;
    if (t < 2 * D) g_stats[t] = 0.f;
}

// ---------------- node SGEMM: g_P[M,512] = x[M,128] @ g_B1[128,512] ----------------
#define BM 64
#define BN 64
#define BK 16
__global__ __launch_bounds__(256) void node_gemm(const float* __restrict__ A, int M)
{
    const float* __restrict__ B = g_B1;
    float* __restrict__ C = g_P;
    const int N = 512;

    __shared__ float As[BK][BM];
    __shared__ float Bs[BK][BN];

    const int tid = threadIdx.x;
    const int row0 = blockIdx.y * BM;
    const int col0 = blockIdx.x * BN;
    const int tr = tid >> 4;
    const int tc = tid & 15;

    const int a_r  = tid >> 2;
    const int a_c4 = (tid & 3) * 4;
    const int b_r  = tid >> 4;
    const int b_c4 = (tid & 15) * 4;

    float acc[4][4];
#pragma unroll
    for (int i = 0; i < 4; i++)
#pragma unroll
        for (int j = 0; j < 4; j++) acc[i][j] = 0.f;

    const int ar = row0 + a_r;
    for (int k0 = 0; k0 < 128; k0 += BK) {
        float4 av = make_float4(0.f, 0.f, 0.f, 0.f);
        if (ar < M) av = *reinterpret_cast<const float4*>(A + (size_t)ar * 128 + k0 + a_c4);
        As[a_c4 + 0][a_r] = av.x;
        As[a_c4 + 1][a_r] = av.y;
        As[a_c4 + 2][a_r] = av.z;
        As[a_c4 + 3][a_r] = av.w;

        float4 bv = *reinterpret_cast<const float4*>(B + (size_t)(k0 + b_r) * N + col0 + b_c4);
        *reinterpret_cast<float4*>(&Bs[b_r][b_c4]) = bv;
        __syncthreads();

#pragma unroll
        for (int k = 0; k < BK; k++) {
            float4 a = *reinterpret_cast<float4*>(&As[k][tr * 4]);
            float4 b = *reinterpret_cast<float4*>(&Bs[k][tc * 4]);
            acc[0][0] += a.x * b.x; acc[0][1] += a.x * b.y; acc[0][2] += a.x * b.z; acc[0][3] += a.x * b.w;
            acc[1][0] += a.y * b.x; acc[1][1] += a.y * b.y; acc[1][2] += a.y * b.z; acc[1][3] += a.y * b.w;
            acc[2][0] += a.z * b.x; acc[2][1] += a.z * b.y; acc[2][2] += a.z * b.z; acc[2][3] += a.z * b.w;
            acc[3][0] += a.w * b.x; acc[3][1] += a.w * b.y; acc[3][2] += a.w * b.z; acc[3][3] += a.w * b.w;
        }
        __syncthreads();
    }

#pragma unroll
    for (int i = 0; i < 4; i++) {
        int row = row0 + tr * 4 + i;
        if (row < M) {
            float4 v = make_float4(acc[i][0], acc[i][1], acc[i][2], acc[i][3]);
            *reinterpret_cast<float4*>(C + (size_t)row * N + col0 + tc * 4) = v;
        }
    }
}

// ---------------- activations ----------------
__device__ __forceinline__ float sigmoidf_(float x) { return 1.f / (1.f + expf(-x)); }
__device__ __forceinline__ float softplusf_(float x) {
    return fmaxf(x, 0.f) + log1pf(expf(-fabsf(x)));
}

// ---------------- fused edge GEMM + gate + scatter (f32x2 mainloop) ----------------
// Per block: 64 edges x 256 output cols. 256 threads = 8 (row groups) x 32 (col groups).
// Each thread: 8 rows (as 4 packed row-pairs) x (4 f-cols + 4 s-cols).
// acc2[p][j] is f32x2 {row 2p, row 2p+1} for column j (j<4: f-col tc*4+j; j>=4: s-col).
#define EBM 64
#define EBK 16
__global__ __launch_bounds__(256, 2) void edge_fused(
    const float* __restrict__ A,      // edge_attr [N_EDGES, 128]
    const int* __restrict__ src, const int* __restrict__ tgt,
    const float* __restrict__ bf, const float* __restrict__ bs)
{
    __shared__ float As[EBK][EBM];
    __shared__ float Bs[EBK][256];
    __shared__ int s_src[EBM];
    __shared__ int s_tgt[EBM];

    const int tid = threadIdx.x;
    const int row0 = blockIdx.x * EBM;
    const int tr = tid >> 5;   // 0..7
    const int tc = tid & 31;   // 0..31

    if (tid < EBM) {
        int r = row0 + tid;
        s_src[tid] = (r < N_EDGES) ? src[r] : 0;
        s_tgt[tid] = (r < N_EDGES) ? tgt[r] : 0;
    }

    const int a_r  = tid >> 2;          // 0..63
    const int a_c4 = (tid & 3) * 4;     // 0,4,8,12
    const int b_r  = tid >> 4;          // 0..15
    const int b_c  = (tid & 15) * 4;    // 0..60

    unsigned long long acc2[4][8];
#pragma unroll
    for (int p = 0; p < 4; p++)
#pragma unroll
        for (int j = 0; j < 8; j++) acc2[p][j] = 0ULL;

    const int ar = row0 + a_r;
    for (int k0 = 0; k0 < 128; k0 += EBK) {
        float4 av = make_float4(0.f, 0.f, 0.f, 0.f);
        if (ar < N_EDGES) av = *reinterpret_cast<const float4*>(A + (size_t)ar * 128 + k0 + a_c4);
        As[a_c4 + 0][a_r] = av.x;
        As[a_c4 + 1][a_r] = av.y;
        As[a_c4 + 2][a_r] = av.z;
        As[a_c4 + 3][a_r] = av.w;

#pragma unroll
        for (int i = 0; i < 4; i++) {
            int col = b_c + i * 64;
            float4 bv = *reinterpret_cast<const float4*>(g_B2 + (size_t)(k0 + b_r) * 256 + col);
            *reinterpret_cast<float4*>(&Bs[b_r][col]) = bv;
        }
        __syncthreads();

#pragma unroll
        for (int k = 0; k < EBK; k++) {
            // A row-pairs: LDS.128 gives {r0,r1},{r2,r3} packed — no pack cost
            ulonglong2 aA = *reinterpret_cast<ulonglong2*>(&As[k][tr * 8]);
            ulonglong2 aB = *reinterpret_cast<ulonglong2*>(&As[k][tr * 8 + 4]);
            unsigned long long ap[4] = {aA.x, aA.y, aB.x, aB.y};

            float4 bF = *reinterpret_cast<float4*>(&Bs[k][tc * 4]);
            float4 bS = *reinterpret_cast<float4*>(&Bs[k][tc * 4 + 128]);
            unsigned long long bb[8];
            bb[0] = pack2(bF.x, bF.x); bb[1] = pack2(bF.y, bF.y);
            bb[2] = pack2(bF.z, bF.z); bb[3] = pack2(bF.w, bF.w);
            bb[4] = pack2(bS.x, bS.x); bb[5] = pack2(bS.y, bS.y);
            bb[6] = pack2(bS.z, bS.z); bb[7] = pack2(bS.w, bS.w);

#pragma unroll
            for (int p = 0; p < 4; p++) {
#pragma unroll
                for (int j = 0; j < 8; j++) fma2(acc2[p][j], ap[p], bb[j]);
            }
        }
        __syncthreads();
    }

    // epilogue: gate + scatter
    const float4 bfv = *reinterpret_cast<const float4*>(bf + tc * 4);
    const float4 bsv = *reinterpret_cast<const float4*>(bs + tc * 4);

#pragma unroll
    for (int p = 0; p < 4; p++) {
        int lr = tr * 8 + 2 * p;
        int r0 = row0 + lr;
        if (r0 >= N_EDGES) break;

        float flo[4], fhi[4], slo[4], shi[4];
#pragma unroll
        for (int j = 0; j < 4; j++) {
            unpack2(acc2[p][j],     flo[j], fhi[j]);
            unpack2(acc2[p][j + 4], slo[j], shi[j]);
        }

#pragma unroll
        for (int h = 0; h < 2; h++) {
            int row = r0 + h;
            if (row >= N_EDGES) break;
            const float* fv = h ? fhi : flo;
            const float* sv = h ? shi : slo;
            int sN = s_src[lr + h];
            int tN = s_tgt[lr + h];

            const float4 pf1 = *reinterpret_cast<const float4*>(g_P + (size_t)sN * 512 + 0   + tc * 4);
            const float4 pf2 = *reinterpret_cast<const float4*>(g_P + (size_t)tN * 512 + 128 + tc * 4);
            const float4 ps1 = *reinterpret_cast<const float4*>(g_P + (size_t)sN * 512 + 256 + tc * 4);
            const float4 ps2 = *reinterpret_cast<const float4*>(g_P + (size_t)tN * 512 + 384 + tc * 4);

            float f0 = fv[0] + pf1.x + pf2.x + bfv.x;
            float f1 = fv[1] + pf1.y + pf2.y + bfv.y;
            float f2 = fv[2] + pf1.z + pf2.z + bfv.z;
            float f3 = fv[3] + pf1.w + pf2.w + bfv.w;
            float s0 = sv[0] + ps1.x + ps2.x + bsv.x;
            float s1 = sv[1] + ps1.y + ps2.y + bsv.y;
            float s2 = sv[2] + ps1.z + ps2.z + bsv.z;
            float s3 = sv[3] + ps1.w + ps2.w + bsv.w;

            float m0 = sigmoidf_(f0) * softplusf_(s0);
            float m1 = sigmoidf_(f1) * softplusf_(s1);
            float m2 = sigmoidf_(f2) * softplusf_(s2);
            float m3 = sigmoidf_(f3) * softplusf_(s3);

            float* dst = g_agg + (size_t)sN * D + tc * 4;
            asm volatile("red.global.add.v4.f32 [%0], {%1, %2, %3, %4};"
                         :: "l"(dst), "f"(m0), "f"(m1), "f"(m2), "f"(m3) : "memory");
        }
    }
}

// ---------------- BN stats ----------------
__global__ __launch_bounds__(128) void bn_stats() {
    const int d = threadIdx.x;
    float sum = 0.f, sq = 0.f;
    for (int n = blockIdx.x; n < N_NODES; n += gridDim.x) {
        float v = g_agg[(size_t)n * D + d];
        sum += v;
        sq += v * v;
    }
    atomicAdd(&g_stats[d], sum);
    atomicAdd(&g_stats[D + d], sq);
}

// ---------------- BN apply + residual + softplus ----------------
__global__ __launch_bounds__(256) void final_kernel(
    const float* __restrict__ x, const float* __restrict__ gamma,
    const float* __restrict__ beta, float* __restrict__ out)
{
    const float invN = 1.0f / (float)N_NODES;
    for (size_t idx = (size_t)blockIdx.x * blockDim.x + threadIdx.x;
         idx < (size_t)N_NODES * D;
         idx += (size_t)gridDim.x * blockDim.x) {
        int d = (int)(idx & (D - 1));
        float mean = g_stats[d] * invN;
        float var = g_stats[D + d] * invN - mean * mean;
        float rstd = rsqrtf(var + BN_EPS);
        float a = (g_agg[idx] - mean) * rstd * gamma[d] + beta[d];
        float v = x[idx] + a;
        out[idx] = softplusf_(v);
    }
}

// ---------------- launch ----------------
extern "C" void kernel_launch(void* const* d_in, const int* in_sizes, int n_in,
                              void* d_out, int out_size) {
    const float* x         = (const float*)d_in[0];
    const float* edge_attr = (const float*)d_in[1];
    const int*   edge_src  = (const int*)d_in[2];
    const int*   edge_tgt  = (const int*)d_in[3];
    const float* Wf        = (const float*)d_in[4];
    const float* bf        = (const float*)d_in[5];
    const float* Ws        = (const float*)d_in[6];
    const float* bs        = (const float*)d_in[7];
    const float* gamma     = (const float*)d_in[8];
    const float* beta      = (const float*)d_in[9];
    float* out = (float*)d_out;

    // 1. repack weights
    prep_weights<<<(128 * 512 + 255) / 256, 256>>>(Wf, Ws);

    // 2. zero agg + stats
    zero_scratch<<<4096, 256>>>();

    // 3. node GEMM: P[50000, 512] = x @ B1
    {
        dim3 grid(512 / BN, (N_NODES + BM - 1) / BM);
        node_gemm<<<grid, 256>>>(x, N_NODES);
    }

    // 4. fused edge GEMM + gate + scatter
    {
        int blocks = (N_EDGES + EBM - 1) / EBM;
        edge_fused<<<blocks, 256>>>(edge_attr, edge_src, edge_tgt, bf, bs);
    }

    // 5. BN stats
    bn_stats<<<512, 128>>>();

    // 6. BN apply + residual + softplus
    final_kernel<<<(N_NODES * D + 255) / 256, 256>>>(x, gamma, beta, out);
}